// round 2
// baseline (speedup 1.0000x reference)
#include <cuda_runtime.h>

// ---------------------------------------------------------------------------
// RelKDAdapter: src_proj = x_src @ W_src ; deg = clamp(count(edge_row),1) ;
// dst = segment_sum(src_proj[edge_col] / deg[edge_row])
// Output layout (return order): dst [N_DST*128] | src_proj [N_SRC*128] | deg [N_DST]
// ---------------------------------------------------------------------------

#define D_SRC 256
#define D_REL 128

// ---------------- GEMM: C[M,128] = A[M,256] @ B[256,128] -------------------
#define BM 128
#define BN 128
#define BK 16

__global__ __launch_bounds__(256) void sgemm_kernel(
    const float* __restrict__ A, const float* __restrict__ B,
    float* __restrict__ C, int M)
{
    __shared__ float As[BK][BM + 4];   // transposed A tile (+4 pad: reduce bank conflicts)
    __shared__ float Bs[BK][BN];

    const int tid  = threadIdx.x;
    const int row0 = blockIdx.x * BM;
    const int tx   = tid & 15;   // 16 col-groups of 8
    const int ty   = tid >> 4;   // 16 row-groups of 8

    float acc[8][8];
    #pragma unroll
    for (int i = 0; i < 8; i++)
        #pragma unroll
        for (int j = 0; j < 8; j++)
            acc[i][j] = 0.f;

    for (int k0 = 0; k0 < D_SRC; k0 += BK) {
        // Load A tile: 128 rows x 16 k  = 512 float4; 256 threads x 2
        #pragma unroll
        for (int i = 0; i < 2; i++) {
            int idx = tid + i * 256;
            int r   = idx >> 2;          // row in tile 0..127
            int c4  = (idx & 3) * 4;     // k offset 0,4,8,12
            int gr  = row0 + r;
            float4 v = make_float4(0.f, 0.f, 0.f, 0.f);
            if (gr < M)
                v = *reinterpret_cast<const float4*>(A + (size_t)gr * D_SRC + k0 + c4);
            As[c4 + 0][r] = v.x;
            As[c4 + 1][r] = v.y;
            As[c4 + 2][r] = v.z;
            As[c4 + 3][r] = v.w;
        }
        // Load B tile: 16 k-rows x 128 = 512 float4; 256 threads x 2
        #pragma unroll
        for (int i = 0; i < 2; i++) {
            int idx = tid + i * 256;
            int r   = idx >> 5;          // k-row 0..15
            int c4  = (idx & 31) * 4;    // col offset
            float4 v = *reinterpret_cast<const float4*>(B + (size_t)(k0 + r) * D_REL + c4);
            *reinterpret_cast<float4*>(&Bs[r][c4]) = v;
        }
        __syncthreads();

        #pragma unroll
        for (int k = 0; k < BK; k++) {
            float a[8], b[8];
            #pragma unroll
            for (int i = 0; i < 8; i++) a[i] = As[k][ty * 8 + i];
            #pragma unroll
            for (int j = 0; j < 8; j++) b[j] = Bs[k][tx * 8 + j];
            #pragma unroll
            for (int i = 0; i < 8; i++)
                #pragma unroll
                for (int j = 0; j < 8; j++)
                    acc[i][j] += a[i] * b[j];
        }
        __syncthreads();
    }

    #pragma unroll
    for (int i = 0; i < 8; i++) {
        int gr = row0 + ty * 8 + i;
        if (gr < M) {
            #pragma unroll
            for (int j = 0; j < 8; j += 4) {
                float4 v = make_float4(acc[i][j], acc[i][j+1], acc[i][j+2], acc[i][j+3]);
                *reinterpret_cast<float4*>(C + (size_t)gr * D_REL + tx * 8 + j) = v;
            }
        }
    }
}

// ---------------- helpers ----------------

__global__ void zero_kernel(float* __restrict__ p, int n) {
    int i = blockIdx.x * blockDim.x + threadIdx.x;
    if (i < n) p[i] = 0.f;
}

__global__ void deg_count_kernel(const int* __restrict__ row,
                                 float* __restrict__ deg, int E) {
    int e = blockIdx.x * blockDim.x + threadIdx.x;
    if (e < E) atomicAdd(&deg[row[e]], 1.0f);
}

__global__ void deg_clamp_kernel(float* __restrict__ deg, int n) {
    int i = blockIdx.x * blockDim.x + threadIdx.x;
    if (i < n) deg[i] = fmaxf(deg[i], 1.0f);
}

// One warp per edge: gather 128 floats of src_proj[col], scale by 1/deg[row],
// atomic-accumulate into dst[row].
__global__ void scatter_kernel(const int* __restrict__ row,
                               const int* __restrict__ col,
                               const float* __restrict__ srcp,
                               const float* __restrict__ deg,
                               float* __restrict__ dst, int E)
{
    int gid  = blockIdx.x * blockDim.x + threadIdx.x;
    int e    = gid >> 5;
    if (e >= E) return;
    int lane = gid & 31;

    int r = __ldg(&row[e]);
    int c = __ldg(&col[e]);
    float invd = 1.0f / __ldg(&deg[r]);

    float4 v = *reinterpret_cast<const float4*>(srcp + (size_t)c * D_REL + lane * 4);
    float* d = dst + (size_t)r * D_REL + lane * 4;
    atomicAdd(d + 0, v.x * invd);
    atomicAdd(d + 1, v.y * invd);
    atomicAdd(d + 2, v.z * invd);
    atomicAdd(d + 3, v.w * invd);
}

// ---------------- launch ----------------

extern "C" void kernel_launch(void* const* d_in, const int* in_sizes, int n_in,
                              void* d_out, int out_size)
{
    const float* x_src    = (const float*)d_in[0];
    // d_in[1] = x_dst (projected but unused by reference output)
    const float* W_src    = (const float*)d_in[2];
    // d_in[3] = W_dst (unused)
    const int*   edge_row = (const int*)d_in[4];
    const int*   edge_col = (const int*)d_in[5];

    const int M    = in_sizes[0] / D_SRC;   // N_SRC
    const int Ndst = in_sizes[1] / 64;      // N_DST
    const int E    = in_sizes[4];

    float* out  = (float*)d_out;
    float* dst  = out;                                 // [Ndst, 128]
    float* srcp = out + (size_t)Ndst * D_REL;          // [M, 128]
    float* deg  = srcp + (size_t)M * D_REL;            // [Ndst]

    // 1) GEMM -> src_proj (lives directly in the output buffer, reused by scatter)
    sgemm_kernel<<<(M + BM - 1) / BM, 256>>>(x_src, W_src, srcp, M);

    // 2) zero dst + deg regions
    zero_kernel<<<((Ndst * D_REL) + 255) / 256, 256>>>(dst, Ndst * D_REL);
    zero_kernel<<<(Ndst + 255) / 256, 256>>>(deg, Ndst);

    // 3) degree count + clamp
    deg_count_kernel<<<(E + 255) / 256, 256>>>(edge_row, deg, E);
    deg_clamp_kernel<<<(Ndst + 255) / 256, 256>>>(deg, Ndst);

    // 4) mean-aggregate scatter (one warp per edge)
    long long total = (long long)E * 32;
    scatter_kernel<<<(int)((total + 255) / 256), 256>>>(edge_row, edge_col, srcp, deg, dst, E);
}

// round 6
// speedup vs baseline: 1.2673x; 1.2673x over previous
#include <cuda_runtime.h>

// ---------------------------------------------------------------------------
// RelKDAdapter:
//   src_proj = x_src @ W_src                  [N_SRC,256]@[256,128]
//   deg      = clamp(count(edge_row), 1)      [N_DST]
//   dst      = segsum(src_proj[col]/deg[row]) [N_DST,128]
// Output: dst | src_proj | deg  (flat float32)
// R2: packed fma.rn.f32x2 GEMM (FFMA-3reg rt=2 cap -> 2x via f32x2);
//     CSR-ized aggregation (no float atomics, warp-per-dst-row gather).
// ---------------------------------------------------------------------------

#define D_SRC 256
#define D_REL 128

#define N_MAX 262144
#define E_MAX 1048576
#define NB_MAX 256          // N_MAX / 1024

__device__ int g_cnt[N_MAX];
__device__ int g_ptr[N_MAX + 1];
__device__ int g_cursor[N_MAX];
__device__ int g_col[E_MAX];
__device__ int g_part[NB_MAX];
__device__ int g_pscan[NB_MAX];

// ------------------------- packed f32x2 helpers ----------------------------
typedef unsigned long long u64;

__device__ __forceinline__ u64 pack2(float lo, float hi) {
    u64 r;
    asm("mov.b64 %0, {%1, %2};" : "=l"(r) : "f"(lo), "f"(hi));
    return r;
}
__device__ __forceinline__ void unpack2(u64 v, float& lo, float& hi) {
    asm("mov.b64 {%0, %1}, %2;" : "=f"(lo), "=f"(hi) : "l"(v));
}
#define FMA2(acc, a, b) \
    asm("fma.rn.f32x2 %0, %1, %2, %0;" : "+l"(acc) : "l"(a), "l"(b))

// ---------------- GEMM: C[M,128] = A[M,256] @ B[256,128] -------------------
#define BM 128
#define BN 128
#define BK 16

__global__ __launch_bounds__(256) void sgemm_kernel(
    const float* __restrict__ A, const float* __restrict__ B,
    float* __restrict__ C, int M)
{
    // A tile stored transposed AND duplicated: As2[k][2r] = As2[k][2r+1] = A[r][k]
    // so a 64-bit LDS yields the broadcast pair for fma.rn.f32x2 directly.
    __shared__ float As2[BK][2 * BM];
    __shared__ float Bs[BK][BN];

    const int tid  = threadIdx.x;
    const int row0 = blockIdx.x * BM;
    const int tx   = tid & 15;   // 16 col-groups of 8
    const int ty   = tid >> 4;   // 16 row-groups of 8

    u64 acc[8][4];
    #pragma unroll
    for (int i = 0; i < 8; i++)
        #pragma unroll
        for (int j = 0; j < 4; j++)
            acc[i][j] = 0ull;

    for (int k0 = 0; k0 < D_SRC; k0 += BK) {
        // Load A tile: 128 rows x 16 k = 512 float4; 256 threads x 2
        #pragma unroll
        for (int i = 0; i < 2; i++) {
            int idx = tid + i * 256;
            int r   = idx >> 2;          // row in tile 0..127
            int c4  = (idx & 3) * 4;     // k offset 0,4,8,12
            int gr  = row0 + r;
            float4 v = make_float4(0.f, 0.f, 0.f, 0.f);
            if (gr < M)
                v = *reinterpret_cast<const float4*>(A + (size_t)gr * D_SRC + k0 + c4);
            As2[c4 + 0][2 * r] = v.x;  As2[c4 + 0][2 * r + 1] = v.x;
            As2[c4 + 1][2 * r] = v.y;  As2[c4 + 1][2 * r + 1] = v.y;
            As2[c4 + 2][2 * r] = v.z;  As2[c4 + 2][2 * r + 1] = v.z;
            As2[c4 + 3][2 * r] = v.w;  As2[c4 + 3][2 * r + 1] = v.w;
        }
        // Load B tile: 16 k-rows x 128 cols = 512 float4; 256 threads x 2
        #pragma unroll
        for (int i = 0; i < 2; i++) {
            int idx = tid + i * 256;
            int r   = idx >> 5;
            int c4  = (idx & 31) * 4;
            float4 v = *reinterpret_cast<const float4*>(B + (size_t)(k0 + r) * D_REL + c4);
            *reinterpret_cast<float4*>(&Bs[r][c4]) = v;
        }
        __syncthreads();

        #pragma unroll
        for (int k = 0; k < BK; k++) {
            u64 a2[8], b2[4];
            #pragma unroll
            for (int i = 0; i < 8; i++)
                a2[i] = *reinterpret_cast<const u64*>(&As2[k][(ty * 8 + i) * 2]);
            #pragma unroll
            for (int j = 0; j < 4; j++)
                b2[j] = *reinterpret_cast<const u64*>(&Bs[k][tx * 8 + 2 * j]);
            #pragma unroll
            for (int i = 0; i < 8; i++)
                #pragma unroll
                for (int j = 0; j < 4; j++)
                    FMA2(acc[i][j], a2[i], b2[j]);
        }
        __syncthreads();
    }

    #pragma unroll
    for (int i = 0; i < 8; i++) {
        int gr = row0 + ty * 8 + i;
        if (gr < M) {
            float o[8];
            #pragma unroll
            for (int j = 0; j < 4; j++)
                unpack2(acc[i][j], o[2 * j], o[2 * j + 1]);
            float* cp = C + (size_t)gr * D_REL + tx * 8;
            *reinterpret_cast<float4*>(cp)     = make_float4(o[0], o[1], o[2], o[3]);
            *reinterpret_cast<float4*>(cp + 4) = make_float4(o[4], o[5], o[6], o[7]);
        }
    }
}

// --------------------------- CSR build -------------------------------------

__global__ void zero_cnt_kernel(int n) {
    int i = blockIdx.x * blockDim.x + threadIdx.x;
    if (i < n) g_cnt[i] = 0;
}

__global__ void count_kernel(const int* __restrict__ row, int E) {
    int e = blockIdx.x * blockDim.x + threadIdx.x;
    if (e < E) atomicAdd(&g_cnt[row[e]], 1);
}

// pass1: per-1024-chunk sums
__global__ void scan_pass1_kernel(int N) {
    __shared__ int s[256];
    int b = blockIdx.x, tid = threadIdx.x;
    int base = b * 1024 + tid * 4;
    int sum = 0;
    #pragma unroll
    for (int i = 0; i < 4; i++) {
        int idx = base + i;
        if (idx < N) sum += g_cnt[idx];
    }
    s[tid] = sum;
    __syncthreads();
    for (int off = 128; off > 0; off >>= 1) {
        if (tid < off) s[tid] += s[tid + off];
        __syncthreads();
    }
    if (tid == 0) g_part[b] = s[0];
}

// pass2: exclusive scan of chunk sums (single block, NB <= 256)
__global__ void scan_pass2_kernel(int NB) {
    __shared__ int s[256];
    int tid = threadIdx.x;
    int own = (tid < NB) ? g_part[tid] : 0;
    s[tid] = own;
    __syncthreads();
    for (int off = 1; off < 256; off <<= 1) {
        int t = (tid >= off) ? s[tid - off] : 0;
        __syncthreads();
        s[tid] += t;
        __syncthreads();
    }
    if (tid < NB) g_pscan[tid] = s[tid] - own;
}

// pass3: write exclusive ptr, cursor, deg=max(cnt,1)
__global__ void scan_pass3_kernel(float* __restrict__ deg, int N, int E) {
    __shared__ int s[256];
    int b = blockIdx.x, tid = threadIdx.x;
    int base = b * 1024 + tid * 4;
    int c[4];
    int sum = 0;
    #pragma unroll
    for (int i = 0; i < 4; i++) {
        int idx = base + i;
        c[i] = (idx < N) ? g_cnt[idx] : 0;
        sum += c[i];
    }
    s[tid] = sum;
    __syncthreads();
    for (int off = 1; off < 256; off <<= 1) {
        int t = (tid >= off) ? s[tid - off] : 0;
        __syncthreads();
        s[tid] += t;
        __syncthreads();
    }
    int pos = g_pscan[b] + s[tid] - sum;   // exclusive offset of this thread's 4
    #pragma unroll
    for (int i = 0; i < 4; i++) {
        int idx = base + i;
        if (idx < N) {
            g_ptr[idx]    = pos;
            g_cursor[idx] = pos;
            deg[idx]      = fmaxf((float)c[i], 1.0f);
            pos += c[i];
        }
    }
    if (b == 0 && tid == 0) g_ptr[N] = E;
}

__global__ void fill_kernel(const int* __restrict__ row,
                            const int* __restrict__ col, int E) {
    int e = blockIdx.x * blockDim.x + threadIdx.x;
    if (e < E) {
        int r = row[e];
        int pos = atomicAdd(&g_cursor[r], 1);
        g_col[pos] = col[e];
    }
}

// -------------------- aggregate: warp per dst row --------------------------
__global__ __launch_bounds__(256) void aggregate_kernel(
    const float* __restrict__ srcp, float* __restrict__ dst, int N)
{
    int warp = (blockIdx.x * blockDim.x + threadIdx.x) >> 5;
    if (warp >= N) return;
    int lane = threadIdx.x & 31;

    int beg = g_ptr[warp];
    int end = g_ptr[warp + 1];

    float4 acc = make_float4(0.f, 0.f, 0.f, 0.f);
    int e = beg;
    for (; e + 1 < end; e += 2) {
        int c0 = g_col[e], c1 = g_col[e + 1];
        float4 v0 = *reinterpret_cast<const float4*>(srcp + (size_t)c0 * D_REL + lane * 4);
        float4 v1 = *reinterpret_cast<const float4*>(srcp + (size_t)c1 * D_REL + lane * 4);
        acc.x += v0.x + v1.x; acc.y += v0.y + v1.y;
        acc.z += v0.z + v1.z; acc.w += v0.w + v1.w;
    }
    if (e < end) {
        int c0 = g_col[e];
        float4 v0 = *reinterpret_cast<const float4*>(srcp + (size_t)c0 * D_REL + lane * 4);
        acc.x += v0.x; acc.y += v0.y; acc.z += v0.z; acc.w += v0.w;
    }

    float invd = 1.0f / fmaxf((float)(end - beg), 1.0f);
    acc.x *= invd; acc.y *= invd; acc.z *= invd; acc.w *= invd;
    *reinterpret_cast<float4*>(dst + (size_t)warp * D_REL + lane * 4) = acc;
}

// ------------------------------ launch -------------------------------------

extern "C" void kernel_launch(void* const* d_in, const int* in_sizes, int n_in,
                              void* d_out, int out_size)
{
    const float* x_src    = (const float*)d_in[0];
    const float* W_src    = (const float*)d_in[2];
    const int*   edge_row = (const int*)d_in[4];
    const int*   edge_col = (const int*)d_in[5];

    const int M    = in_sizes[0] / D_SRC;   // N_SRC
    const int Ndst = in_sizes[1] / 64;      // N_DST
    const int E    = in_sizes[4];

    float* out  = (float*)d_out;
    float* dst  = out;                                 // [Ndst, 128]
    float* srcp = out + (size_t)Ndst * D_REL;          // [M, 128]
    float* deg  = srcp + (size_t)M * D_REL;            // [Ndst]

    const int NB = (Ndst + 1023) / 1024;

    // GEMM (longest) first
    sgemm_kernel<<<(M + BM - 1) / BM, 256>>>(x_src, W_src, srcp, M);

    // CSR build
    zero_cnt_kernel<<<(Ndst + 255) / 256, 256>>>(Ndst);
    count_kernel<<<(E + 255) / 256, 256>>>(edge_row, E);
    scan_pass1_kernel<<<NB, 256>>>(Ndst);
    scan_pass2_kernel<<<1, 256>>>(NB);
    scan_pass3_kernel<<<NB, 256>>>(deg, Ndst, E);
    fill_kernel<<<(E + 255) / 256, 256>>>(edge_row, edge_col, E);

    // Gather-aggregate (no float atomics), writes all dst rows (incl. zeros)
    aggregate_kernel<<<(Ndst * 32 + 255) / 256, 256>>>(srcp, dst, Ndst);
}

// round 13
// speedup vs baseline: 2.4502x; 1.9334x over previous
#include <cuda_runtime.h>
#include <cuda_bf16.h>
#include <cstdint>

// ---------------------------------------------------------------------------
// RelKDAdapter:
//   src_proj = x_src @ W_src                  [N_SRC,256]@[256,128]
//   deg      = clamp(count(edge_row), 1)      [N_DST]
//   dst      = segsum(src_proj[col]/deg[row]) [N_DST,128]
// Output: dst | src_proj | deg  (flat float32)
// R12: fix B-fragment load — K-major [n][k] B needs ldmatrix NON-trans
//      (trans is for MN-major [k][n]). Rest identical to R10.
// ---------------------------------------------------------------------------

#define D_SRC 256
#define D_REL 128

#define N_MAX 262144
#define E_MAX 1048576
#define NB_MAX 256

__device__ int g_cnt[N_MAX];
__device__ int g_ptr[N_MAX + 1];
__device__ int g_cursor[N_MAX];
__device__ int g_col[E_MAX];
__device__ int g_part[NB_MAX];
__device__ int g_pscan[NB_MAX];

// W^T split into bf16 hi/lo: [128 n-rows][256 k]
__device__ __nv_bfloat16 g_wt_hi[D_REL * D_SRC];
__device__ __nv_bfloat16 g_wt_lo[D_REL * D_SRC];

// ------------------------- helpers -----------------------------------------

__device__ __forceinline__ uint32_t smem_u32(const void* p) {
    uint32_t a;
    asm("{ .reg .u64 t; cvta.to.shared.u64 t, %1; cvt.u32.u64 %0, t; }"
        : "=r"(a) : "l"(p));
    return a;
}

#define SW128(off) ((off) ^ (((off) >> 3) & 0x70))

__device__ __forceinline__ void ldm_x4(uint32_t* r, uint32_t addr) {
    asm volatile("ldmatrix.sync.aligned.m8n8.x4.shared.b16 {%0,%1,%2,%3}, [%4];"
                 : "=r"(r[0]), "=r"(r[1]), "=r"(r[2]), "=r"(r[3]) : "r"(addr));
}
__device__ __forceinline__ void mma_bf16(float* d, const uint32_t* a,
                                         uint32_t b0, uint32_t b1) {
    asm volatile(
        "mma.sync.aligned.m16n8k16.row.col.f32.bf16.bf16.f32 "
        "{%0,%1,%2,%3}, {%4,%5,%6,%7}, {%8,%9}, {%0,%1,%2,%3};"
        : "+f"(d[0]), "+f"(d[1]), "+f"(d[2]), "+f"(d[3])
        : "r"(a[0]), "r"(a[1]), "r"(a[2]), "r"(a[3]), "r"(b0), "r"(b1));
}

// --------------------- W transpose + bf16 split ----------------------------

__global__ void wsplit_kernel(const float* __restrict__ W) {
    int i = blockIdx.x * blockDim.x + threadIdx.x;
    if (i < D_SRC * D_REL) {
        int k = i >> 7;          // 0..255
        int n = i & 127;         // 0..127
        float v = W[i];          // W[k][n]
        __nv_bfloat16 h = __float2bfloat16(v);
        g_wt_hi[n * D_SRC + k] = h;
        g_wt_lo[n * D_SRC + k] = __float2bfloat16(v - __bfloat162float(h));
    }
}

// --------------------- HMMA GEMM -------------------------------------------
// Per CTA: C[128, 128] = A[128, 256] @ W^T, bf16 hi/lo 3-term split.
// SMEM (dynamic): A_hi[128x64] | A_lo | B_hi[128n x 64k] | B_lo, bf16, SW128.
// Warp w computes rows [16w, 16w+16) x all 128 cols (16 n-tiles of 8).

#define OFF_AH 0
#define OFF_AL 16384
#define OFF_BH 32768
#define OFF_BL 49152
#define GEMM_SMEM (65536 + 128)

__global__ __launch_bounds__(256) void mma_gemm_kernel(
    const float* __restrict__ A, float* __restrict__ C, int M)
{
    extern __shared__ char smraw[];
    uint32_t rawb = smem_u32(smraw);
    uint32_t smb  = (rawb + 127u) & ~127u;
    char*    sm   = smraw + (smb - rawb);

    const int tid  = threadIdx.x;
    const int wid  = tid >> 5;
    const int lane = tid & 31;
    const int row0 = blockIdx.x * 128;
    const int warp_m = wid * 16;

    float acc[16][4];
    #pragma unroll
    for (int t = 0; t < 16; t++)
        #pragma unroll
        for (int q = 0; q < 4; q++)
            acc[t][q] = 0.f;

    // ldmatrix per-lane source rows (computed once)
    const int tpid  = lane >> 3;   // tile index within x4
    const int rowin = lane & 7;
    const int a_m   = warp_m + (tpid & 1) * 8 + rowin;     // A: t0/t2 rows m0-7, t1/t3 m8-15
    const int a_kb0 = (tpid >> 1) * 16;                     // A: t2/t3 at k-bytes +16
    const int b_kb0 = (tpid & 1) * 16;                      // B: t1/t3 at k-bytes +16
    const int b_nrw = (tpid >> 1) * 8 + rowin;              // B: t2/t3 rows n8-15

    for (int kc = 0; kc < 4; kc++) {
        // ---- load + convert A chunk [128 x 64] fp32 -> bf16 hi/lo ----
        #pragma unroll
        for (int i = 0; i < 4; i++) {
            int idx = tid + i * 256;     // 0..1023
            int r   = idx >> 3;
            int k0  = (idx & 7) * 8;
            int gr  = row0 + r;
            float4 v0 = make_float4(0.f, 0.f, 0.f, 0.f);
            float4 v1 = v0;
            if (gr < M) {
                const float* ap = A + (size_t)gr * D_SRC + kc * 64 + k0;
                v0 = *reinterpret_cast<const float4*>(ap);
                v1 = *reinterpret_cast<const float4*>(ap + 4);
            }
            float fv[8] = {v0.x, v0.y, v0.z, v0.w, v1.x, v1.y, v1.z, v1.w};
            __nv_bfloat16 h[8], l[8];
            #pragma unroll
            for (int j = 0; j < 8; j++) {
                h[j] = __float2bfloat16(fv[j]);
                l[j] = __float2bfloat16(fv[j] - __bfloat162float(h[j]));
            }
            uint32_t off = SW128(r * 128 + k0 * 2);
            *reinterpret_cast<uint4*>(sm + OFF_AH + off) = *reinterpret_cast<uint4*>(h);
            *reinterpret_cast<uint4*>(sm + OFF_AL + off) = *reinterpret_cast<uint4*>(l);
        }
        // ---- load B chunk [128 n x 64 k] hi/lo from pre-split global ----
        #pragma unroll
        for (int i = 0; i < 4; i++) {
            int idx = tid + i * 256;
            int r   = idx >> 3;
            int k0  = (idx & 7) * 8;
            uint4 vh = *reinterpret_cast<const uint4*>(g_wt_hi + r * D_SRC + kc * 64 + k0);
            uint4 vl = *reinterpret_cast<const uint4*>(g_wt_lo + r * D_SRC + kc * 64 + k0);
            uint32_t off = SW128(r * 128 + k0 * 2);
            *reinterpret_cast<uint4*>(sm + OFF_BH + off) = vh;
            *reinterpret_cast<uint4*>(sm + OFF_BL + off) = vl;
        }
        __syncthreads();

        #pragma unroll
        for (int ks = 0; ks < 4; ks++) {
            const int kb = ks * 32;   // byte offset within 128B row
            uint32_t ah[4], al[4];
            ldm_x4(ah, smb + OFF_AH + SW128(a_m * 128 + kb + a_kb0));
            ldm_x4(al, smb + OFF_AL + SW128(a_m * 128 + kb + a_kb0));

            #pragma unroll
            for (int p = 0; p < 8; p++) {
                uint32_t bh[4], bl[4];
                uint32_t boff = SW128((p * 16 + b_nrw) * 128 + kb + b_kb0);
                // K-major [n][k] B: NON-trans ldmatrix yields the col-major
                // k16n8 fragment (lane -> (n=l>>2, k=2(l&3)+{0,1})).
                ldm_x4(bh, smb + OFF_BH + boff);
                ldm_x4(bl, smb + OFF_BL + boff);
                // n-tile 2p
                mma_bf16(acc[2 * p],     ah, bh[0], bh[1]);
                mma_bf16(acc[2 * p],     ah, bl[0], bl[1]);
                mma_bf16(acc[2 * p],     al, bh[0], bh[1]);
                // n-tile 2p+1
                mma_bf16(acc[2 * p + 1], ah, bh[2], bh[3]);
                mma_bf16(acc[2 * p + 1], ah, bl[2], bl[3]);
                mma_bf16(acc[2 * p + 1], al, bh[2], bh[3]);
            }
        }
        __syncthreads();
    }

    // ---- epilogue ----
    int r_lo = row0 + warp_m + (lane >> 2);
    int cb   = (lane & 3) * 2;
    #pragma unroll
    for (int nt = 0; nt < 16; nt++) {
        int col = nt * 8 + cb;
        if (r_lo < M)
            *reinterpret_cast<float2*>(C + (size_t)r_lo * D_REL + col) =
                make_float2(acc[nt][0], acc[nt][1]);
        if (r_lo + 8 < M)
            *reinterpret_cast<float2*>(C + (size_t)(r_lo + 8) * D_REL + col) =
                make_float2(acc[nt][2], acc[nt][3]);
    }
}

// --------------------------- CSR build -------------------------------------

__global__ void zero_cnt_kernel(int n) {
    int i = blockIdx.x * blockDim.x + threadIdx.x;
    if (i < n) g_cnt[i] = 0;
}

__global__ void count_kernel(const int* __restrict__ row, int E) {
    int e = blockIdx.x * blockDim.x + threadIdx.x;
    if (e < E) atomicAdd(&g_cnt[row[e]], 1);
}

__global__ void scan_pass1_kernel(int N) {
    __shared__ int s[256];
    int b = blockIdx.x, tid = threadIdx.x;
    int base = b * 1024 + tid * 4;
    int sum = 0;
    #pragma unroll
    for (int i = 0; i < 4; i++) {
        int idx = base + i;
        if (idx < N) sum += g_cnt[idx];
    }
    s[tid] = sum;
    __syncthreads();
    for (int off = 128; off > 0; off >>= 1) {
        if (tid < off) s[tid] += s[tid + off];
        __syncthreads();
    }
    if (tid == 0) g_part[b] = s[0];
}

__global__ void scan_pass2_kernel(int NB) {
    __shared__ int s[256];
    int tid = threadIdx.x;
    int own = (tid < NB) ? g_part[tid] : 0;
    s[tid] = own;
    __syncthreads();
    for (int off = 1; off < 256; off <<= 1) {
        int t = (tid >= off) ? s[tid - off] : 0;
        __syncthreads();
        s[tid] += t;
        __syncthreads();
    }
    if (tid < NB) g_pscan[tid] = s[tid] - own;
}

__global__ void scan_pass3_kernel(float* __restrict__ deg, int N, int E) {
    __shared__ int s[256];
    int b = blockIdx.x, tid = threadIdx.x;
    int base = b * 1024 + tid * 4;
    int c[4];
    int sum = 0;
    #pragma unroll
    for (int i = 0; i < 4; i++) {
        int idx = base + i;
        c[i] = (idx < N) ? g_cnt[idx] : 0;
        sum += c[i];
    }
    s[tid] = sum;
    __syncthreads();
    for (int off = 1; off < 256; off <<= 1) {
        int t = (tid >= off) ? s[tid - off] : 0;
        __syncthreads();
        s[tid] += t;
        __syncthreads();
    }
    int pos = g_pscan[b] + s[tid] - sum;
    #pragma unroll
    for (int i = 0; i < 4; i++) {
        int idx = base + i;
        if (idx < N) {
            g_ptr[idx]    = pos;
            g_cursor[idx] = pos;
            deg[idx]      = fmaxf((float)c[i], 1.0f);
            pos += c[i];
        }
    }
    if (b == 0 && tid == 0) g_ptr[N] = E;
}

__global__ void fill_kernel(const int* __restrict__ row,
                            const int* __restrict__ col, int E) {
    int e = blockIdx.x * blockDim.x + threadIdx.x;
    if (e < E) {
        int r = row[e];
        int pos = atomicAdd(&g_cursor[r], 1);
        g_col[pos] = col[e];
    }
}

// -------------------- aggregate: warp per dst row --------------------------

__global__ __launch_bounds__(256) void aggregate_kernel(
    const float* __restrict__ srcp, float* __restrict__ dst, int N)
{
    int warp = (blockIdx.x * blockDim.x + threadIdx.x) >> 5;
    if (warp >= N) return;
    int lane = threadIdx.x & 31;

    int beg = g_ptr[warp];
    int end = g_ptr[warp + 1];

    float4 acc = make_float4(0.f, 0.f, 0.f, 0.f);
    int e = beg;
    for (; e + 1 < end; e += 2) {
        int c0 = g_col[e], c1 = g_col[e + 1];
        float4 v0 = *reinterpret_cast<const float4*>(srcp + (size_t)c0 * D_REL + lane * 4);
        float4 v1 = *reinterpret_cast<const float4*>(srcp + (size_t)c1 * D_REL + lane * 4);
        acc.x += v0.x + v1.x; acc.y += v0.y + v1.y;
        acc.z += v0.z + v1.z; acc.w += v0.w + v1.w;
    }
    if (e < end) {
        int c0 = g_col[e];
        float4 v0 = *reinterpret_cast<const float4*>(srcp + (size_t)c0 * D_REL + lane * 4);
        acc.x += v0.x; acc.y += v0.y; acc.z += v0.z; acc.w += v0.w;
    }

    float invd = 1.0f / fmaxf((float)(end - beg), 1.0f);
    acc.x *= invd; acc.y *= invd; acc.z *= invd; acc.w *= invd;
    *reinterpret_cast<float4*>(dst + (size_t)warp * D_REL + lane * 4) = acc;
}

// ------------------------------ launch -------------------------------------

extern "C" void kernel_launch(void* const* d_in, const int* in_sizes, int n_in,
                              void* d_out, int out_size)
{
    const float* x_src    = (const float*)d_in[0];
    const float* W_src    = (const float*)d_in[2];
    const int*   edge_row = (const int*)d_in[4];
    const int*   edge_col = (const int*)d_in[5];

    const int M    = in_sizes[0] / D_SRC;   // N_SRC
    const int Ndst = in_sizes[1] / 64;      // N_DST
    const int E    = in_sizes[4];

    float* out  = (float*)d_out;
    float* dst  = out;                                 // [Ndst, 128]
    float* srcp = out + (size_t)Ndst * D_REL;          // [M, 128]
    float* deg  = srcp + (size_t)M * D_REL;            // [Ndst]

    const int NB = (Ndst + 1023) / 1024;

    cudaFuncSetAttribute(mma_gemm_kernel,
                         cudaFuncAttributeMaxDynamicSharedMemorySize, GEMM_SMEM);

    // W split/transpose (tiny), then tensor-core GEMM
    wsplit_kernel<<<(D_SRC * D_REL + 255) / 256, 256>>>(W_src);
    mma_gemm_kernel<<<(M + 127) / 128, 256, GEMM_SMEM>>>(x_src, srcp, M);

    // CSR build
    zero_cnt_kernel<<<(Ndst + 255) / 256, 256>>>(Ndst);
    count_kernel<<<(E + 255) / 256, 256>>>(edge_row, E);
    scan_pass1_kernel<<<NB, 256>>>(Ndst);
    scan_pass2_kernel<<<1, 256>>>(NB);
    scan_pass3_kernel<<<NB, 256>>>(edge_row ? (float*)(srcp + (size_t)M * D_REL) : deg, Ndst, E);
    fill_kernel<<<(E + 255) / 256, 256>>>(edge_row, edge_col, E);

    // Gather-aggregate (needs srcp + CSR)
    aggregate_kernel<<<(Ndst * 32 + 255) / 256, 256>>>(srcp, dst, Ndst);
}

// round 16
// speedup vs baseline: 2.4776x; 1.0112x over previous
#include <cuda_runtime.h>
#include <cuda_bf16.h>
#include <cstdint>

// ---------------------------------------------------------------------------
// RelKDAdapter:
//   src_proj = x_src @ W_src                  [N_SRC,256]@[256,128]
//   deg      = clamp(count(edge_row), 1)      [N_DST]
//   dst      = segsum(src_proj[col]/deg[row]) [N_DST,128]
// Output: dst | src_proj | deg  (flat float32)
// R15: revert stream fork (capture-illegal). CSR scan (3 kernels) replaced by
//      single atomic bump-allocator kernel (segments contiguous per row but
//      unordered across rows — aggregate only needs beg + cnt).
//      GEMM / aggregate unchanged from the 156 µs WIN.
// ---------------------------------------------------------------------------

#define D_SRC 256
#define D_REL 128

#define N_MAX 262144
#define E_MAX 1048576

__device__ int g_cnt[N_MAX];
__device__ int g_ptr[N_MAX];      // segment begin per row
__device__ int g_cursor[N_MAX];
__device__ int g_col[E_MAX];
__device__ int g_total;

// W^T split into bf16 hi/lo: [128 n-rows][256 k]
__device__ __nv_bfloat16 g_wt_hi[D_REL * D_SRC];
__device__ __nv_bfloat16 g_wt_lo[D_REL * D_SRC];

// ------------------------- helpers -----------------------------------------

__device__ __forceinline__ uint32_t smem_u32(const void* p) {
    uint32_t a;
    asm("{ .reg .u64 t; cvta.to.shared.u64 t, %1; cvt.u32.u64 %0, t; }"
        : "=r"(a) : "l"(p));
    return a;
}

#define SW128(off) ((off) ^ (((off) >> 3) & 0x70))

__device__ __forceinline__ void ldm_x4(uint32_t* r, uint32_t addr) {
    asm volatile("ldmatrix.sync.aligned.m8n8.x4.shared.b16 {%0,%1,%2,%3}, [%4];"
                 : "=r"(r[0]), "=r"(r[1]), "=r"(r[2]), "=r"(r[3]) : "r"(addr));
}
__device__ __forceinline__ void mma_bf16(float* d, const uint32_t* a,
                                         uint32_t b0, uint32_t b1) {
    asm volatile(
        "mma.sync.aligned.m16n8k16.row.col.f32.bf16.bf16.f32 "
        "{%0,%1,%2,%3}, {%4,%5,%6,%7}, {%8,%9}, {%0,%1,%2,%3};"
        : "+f"(d[0]), "+f"(d[1]), "+f"(d[2]), "+f"(d[3])
        : "r"(a[0]), "r"(a[1]), "r"(a[2]), "r"(a[3]), "r"(b0), "r"(b1));
}

// --------------------- W transpose + bf16 split ----------------------------

__global__ void wsplit_kernel(const float* __restrict__ W) {
    int i = blockIdx.x * blockDim.x + threadIdx.x;
    if (i < D_SRC * D_REL) {
        int k = i >> 7;          // 0..255
        int n = i & 127;         // 0..127
        float v = W[i];          // W[k][n]
        __nv_bfloat16 h = __float2bfloat16(v);
        g_wt_hi[n * D_SRC + k] = h;
        g_wt_lo[n * D_SRC + k] = __float2bfloat16(v - __bfloat162float(h));
    }
}

// --------------------- HMMA GEMM (unchanged from 156 µs WIN) ---------------

#define OFF_AH 0
#define OFF_AL 16384
#define OFF_BH 32768
#define OFF_BL 49152
#define GEMM_SMEM (65536 + 128)

__global__ __launch_bounds__(256) void mma_gemm_kernel(
    const float* __restrict__ A, float* __restrict__ C, int M)
{
    extern __shared__ char smraw[];
    uint32_t rawb = smem_u32(smraw);
    uint32_t smb  = (rawb + 127u) & ~127u;
    char*    sm   = smraw + (smb - rawb);

    const int tid  = threadIdx.x;
    const int wid  = tid >> 5;
    const int lane = tid & 31;
    const int row0 = blockIdx.x * 128;
    const int warp_m = wid * 16;

    float acc[16][4];
    #pragma unroll
    for (int t = 0; t < 16; t++)
        #pragma unroll
        for (int q = 0; q < 4; q++)
            acc[t][q] = 0.f;

    const int tpid  = lane >> 3;
    const int rowin = lane & 7;
    const int a_m   = warp_m + (tpid & 1) * 8 + rowin;
    const int a_kb0 = (tpid >> 1) * 16;
    const int b_kb0 = (tpid & 1) * 16;
    const int b_nrw = (tpid >> 1) * 8 + rowin;

    for (int kc = 0; kc < 4; kc++) {
        #pragma unroll
        for (int i = 0; i < 4; i++) {
            int idx = tid + i * 256;
            int r   = idx >> 3;
            int k0  = (idx & 7) * 8;
            int gr  = row0 + r;
            float4 v0 = make_float4(0.f, 0.f, 0.f, 0.f);
            float4 v1 = v0;
            if (gr < M) {
                const float* ap = A + (size_t)gr * D_SRC + kc * 64 + k0;
                v0 = *reinterpret_cast<const float4*>(ap);
                v1 = *reinterpret_cast<const float4*>(ap + 4);
            }
            float fv[8] = {v0.x, v0.y, v0.z, v0.w, v1.x, v1.y, v1.z, v1.w};
            __nv_bfloat16 h[8], l[8];
            #pragma unroll
            for (int j = 0; j < 8; j++) {
                h[j] = __float2bfloat16(fv[j]);
                l[j] = __float2bfloat16(fv[j] - __bfloat162float(h[j]));
            }
            uint32_t off = SW128(r * 128 + k0 * 2);
            *reinterpret_cast<uint4*>(sm + OFF_AH + off) = *reinterpret_cast<uint4*>(h);
            *reinterpret_cast<uint4*>(sm + OFF_AL + off) = *reinterpret_cast<uint4*>(l);
        }
        #pragma unroll
        for (int i = 0; i < 4; i++) {
            int idx = tid + i * 256;
            int r   = idx >> 3;
            int k0  = (idx & 7) * 8;
            uint4 vh = *reinterpret_cast<const uint4*>(g_wt_hi + r * D_SRC + kc * 64 + k0);
            uint4 vl = *reinterpret_cast<const uint4*>(g_wt_lo + r * D_SRC + kc * 64 + k0);
            uint32_t off = SW128(r * 128 + k0 * 2);
            *reinterpret_cast<uint4*>(sm + OFF_BH + off) = vh;
            *reinterpret_cast<uint4*>(sm + OFF_BL + off) = vl;
        }
        __syncthreads();

        #pragma unroll
        for (int ks = 0; ks < 4; ks++) {
            const int kb = ks * 32;
            uint32_t ah[4], al[4];
            ldm_x4(ah, smb + OFF_AH + SW128(a_m * 128 + kb + a_kb0));
            ldm_x4(al, smb + OFF_AL + SW128(a_m * 128 + kb + a_kb0));

            #pragma unroll
            for (int p = 0; p < 8; p++) {
                uint32_t bh[4], bl[4];
                uint32_t boff = SW128((p * 16 + b_nrw) * 128 + kb + b_kb0);
                ldm_x4(bh, smb + OFF_BH + boff);
                ldm_x4(bl, smb + OFF_BL + boff);
                mma_bf16(acc[2 * p],     ah, bh[0], bh[1]);
                mma_bf16(acc[2 * p],     ah, bl[0], bl[1]);
                mma_bf16(acc[2 * p],     al, bh[0], bh[1]);
                mma_bf16(acc[2 * p + 1], ah, bh[2], bh[3]);
                mma_bf16(acc[2 * p + 1], ah, bl[2], bl[3]);
                mma_bf16(acc[2 * p + 1], al, bh[2], bh[3]);
            }
        }
        __syncthreads();
    }

    int r_lo = row0 + warp_m + (lane >> 2);
    int cb   = (lane & 3) * 2;
    #pragma unroll
    for (int nt = 0; nt < 16; nt++) {
        int col = nt * 8 + cb;
        if (r_lo < M)
            *reinterpret_cast<float2*>(C + (size_t)r_lo * D_REL + col) =
                make_float2(acc[nt][0], acc[nt][1]);
        if (r_lo + 8 < M)
            *reinterpret_cast<float2*>(C + (size_t)(r_lo + 8) * D_REL + col) =
                make_float2(acc[nt][2], acc[nt][3]);
    }
}

// --------------------------- CSR build -------------------------------------

__global__ void zero_cnt_kernel(int n) {
    int i = blockIdx.x * blockDim.x + threadIdx.x;
    if (i < n) g_cnt[i] = 0;
    if (i == 0) g_total = 0;
}

__global__ void count_kernel(const int* __restrict__ row, int E) {
    int e = blockIdx.x * blockDim.x + threadIdx.x;
    if (e < E) atomicAdd(&g_cnt[row[e]], 1);
}

// Bump allocator: contiguous segment per row, rows unordered globally.
// Fuses the old 3-pass scan into one kernel; also writes deg.
__global__ void alloc_kernel(float* __restrict__ deg, int N) {
    __shared__ int s[256];
    __shared__ int blockBase;
    int b = blockIdx.x, tid = threadIdx.x;
    int base = b * 1024 + tid * 4;

    int c[4];
    int sum = 0;
    #pragma unroll
    for (int i = 0; i < 4; i++) {
        int idx = base + i;
        c[i] = (idx < N) ? g_cnt[idx] : 0;
        sum += c[i];
    }
    s[tid] = sum;
    __syncthreads();
    // inclusive scan over block
    for (int off = 1; off < 256; off <<= 1) {
        int t = (tid >= off) ? s[tid - off] : 0;
        __syncthreads();
        s[tid] += t;
        __syncthreads();
    }
    if (tid == 255) blockBase = atomicAdd(&g_total, s[255]);
    __syncthreads();

    int pos = blockBase + s[tid] - sum;   // exclusive offset within block alloc
    #pragma unroll
    for (int i = 0; i < 4; i++) {
        int idx = base + i;
        if (idx < N) {
            g_ptr[idx]    = pos;
            g_cursor[idx] = pos;
            deg[idx]      = fmaxf((float)c[i], 1.0f);
            pos += c[i];
        }
    }
}

__global__ void fill_kernel(const int* __restrict__ row,
                            const int* __restrict__ col, int E) {
    int e = blockIdx.x * blockDim.x + threadIdx.x;
    if (e < E) {
        int r = row[e];
        int pos = atomicAdd(&g_cursor[r], 1);
        g_col[pos] = col[e];
    }
}

// -------------------- aggregate: warp per dst row --------------------------

__global__ __launch_bounds__(256) void aggregate_kernel(
    const float* __restrict__ srcp, float* __restrict__ dst, int N)
{
    int warp = (blockIdx.x * blockDim.x + threadIdx.x) >> 5;
    if (warp >= N) return;
    int lane = threadIdx.x & 31;

    int beg = g_ptr[warp];
    int cnt = g_cnt[warp];
    int end = beg + cnt;

    float4 acc = make_float4(0.f, 0.f, 0.f, 0.f);
    int e = beg;
    for (; e + 1 < end; e += 2) {
        int c0 = g_col[e], c1 = g_col[e + 1];
        float4 v0 = *reinterpret_cast<const float4*>(srcp + (size_t)c0 * D_REL + lane * 4);
        float4 v1 = *reinterpret_cast<const float4*>(srcp + (size_t)c1 * D_REL + lane * 4);
        acc.x += v0.x + v1.x; acc.y += v0.y + v1.y;
        acc.z += v0.z + v1.z; acc.w += v0.w + v1.w;
    }
    if (e < end) {
        int c0 = g_col[e];
        float4 v0 = *reinterpret_cast<const float4*>(srcp + (size_t)c0 * D_REL + lane * 4);
        acc.x += v0.x; acc.y += v0.y; acc.z += v0.z; acc.w += v0.w;
    }

    float invd = 1.0f / fmaxf((float)cnt, 1.0f);
    acc.x *= invd; acc.y *= invd; acc.z *= invd; acc.w *= invd;
    *reinterpret_cast<float4*>(dst + (size_t)warp * D_REL + lane * 4) = acc;
}

// ------------------------------ launch -------------------------------------

extern "C" void kernel_launch(void* const* d_in, const int* in_sizes, int n_in,
                              void* d_out, int out_size)
{
    const float* x_src    = (const float*)d_in[0];
    const float* W_src    = (const float*)d_in[2];
    const int*   edge_row = (const int*)d_in[4];
    const int*   edge_col = (const int*)d_in[5];

    const int M    = in_sizes[0] / D_SRC;   // N_SRC
    const int Ndst = in_sizes[1] / 64;      // N_DST
    const int E    = in_sizes[4];

    float* out  = (float*)d_out;
    float* dst  = out;                                 // [Ndst, 128]
    float* srcp = out + (size_t)Ndst * D_REL;          // [M, 128]
    float* deg  = srcp + (size_t)M * D_REL;            // [Ndst]

    const int NB = (Ndst + 1023) / 1024;

    static int once = 0;
    if (!once) {
        cudaFuncSetAttribute(mma_gemm_kernel,
                             cudaFuncAttributeMaxDynamicSharedMemorySize, GEMM_SMEM);
        once = 1;
    }

    // W split + tensor-core GEMM
    wsplit_kernel<<<(D_SRC * D_REL + 255) / 256, 256>>>(W_src);
    mma_gemm_kernel<<<(M + 127) / 128, 256, GEMM_SMEM>>>(x_src, srcp, M);

    // CSR build: zero -> count -> bump-alloc -> fill
    zero_cnt_kernel<<<(Ndst + 255) / 256, 256>>>(Ndst);
    count_kernel<<<(E + 255) / 256, 256>>>(edge_row, E);
    alloc_kernel<<<NB, 256>>>(deg, Ndst);
    fill_kernel<<<(E + 255) / 256, 256>>>(edge_row, edge_col, E);

    // Gather-aggregate
    aggregate_kernel<<<(Ndst * 32 + 255) / 256, 256>>>(srcp, dst, Ndst);
}

// round 17
// speedup vs baseline: 2.6846x; 1.0836x over previous
#include <cuda_runtime.h>
#include <cuda_bf16.h>
#include <cstdint>

// ---------------------------------------------------------------------------
// RelKDAdapter:
//   src_proj = x_src @ W_src                  [N_SRC,256]@[256,128]
//   deg      = clamp(count(edge_row), 1)      [N_DST]
//   dst      = segsum(src_proj[col]/deg[row]) [N_DST,128]
// Output: dst | src_proj | deg  (flat float32)
// R16: GEMM retile — warps 4(m) x 2(n), each 32 rows x 64 cols so every B
//      fragment feeds 2 m-tiles (LDSM per k-slice 18 -> 12); B staged via
//      cp.async.cg overlapping the A fp32->bf16 convert. CSR/aggregate
//      unchanged from the 154.4 us baseline.
// ---------------------------------------------------------------------------

#define D_SRC 256
#define D_REL 128

#define N_MAX 262144
#define E_MAX 1048576

__device__ int g_cnt[N_MAX];
__device__ int g_ptr[N_MAX];      // segment begin per row
__device__ int g_cursor[N_MAX];
__device__ int g_col[E_MAX];
__device__ int g_total;

// W^T split into bf16 hi/lo: [128 n-rows][256 k]
__device__ __nv_bfloat16 g_wt_hi[D_REL * D_SRC];
__device__ __nv_bfloat16 g_wt_lo[D_REL * D_SRC];

// ------------------------- helpers -----------------------------------------

__device__ __forceinline__ uint32_t smem_u32(const void* p) {
    uint32_t a;
    asm("{ .reg .u64 t; cvta.to.shared.u64 t, %1; cvt.u32.u64 %0, t; }"
        : "=r"(a) : "l"(p));
    return a;
}

#define SW128(off) ((off) ^ (((off) >> 3) & 0x70))

__device__ __forceinline__ void ldm_x4(uint32_t* r, uint32_t addr) {
    asm volatile("ldmatrix.sync.aligned.m8n8.x4.shared.b16 {%0,%1,%2,%3}, [%4];"
                 : "=r"(r[0]), "=r"(r[1]), "=r"(r[2]), "=r"(r[3]) : "r"(addr));
}
__device__ __forceinline__ void mma_bf16(float* d, const uint32_t* a,
                                         uint32_t b0, uint32_t b1) {
    asm volatile(
        "mma.sync.aligned.m16n8k16.row.col.f32.bf16.bf16.f32 "
        "{%0,%1,%2,%3}, {%4,%5,%6,%7}, {%8,%9}, {%0,%1,%2,%3};"
        : "+f"(d[0]), "+f"(d[1]), "+f"(d[2]), "+f"(d[3])
        : "r"(a[0]), "r"(a[1]), "r"(a[2]), "r"(a[3]), "r"(b0), "r"(b1));
}

#define CP_ASYNC16(dst, src) \
    asm volatile("cp.async.cg.shared.global [%0], [%1], 16;" \
                 :: "r"(dst), "l"(src) : "memory")
#define CP_COMMIT()  asm volatile("cp.async.commit_group;" ::: "memory")
#define CP_WAIT0()   asm volatile("cp.async.wait_group 0;" ::: "memory")

// --------------------- W transpose + bf16 split ----------------------------

__global__ void wsplit_kernel(const float* __restrict__ W) {
    int i = blockIdx.x * blockDim.x + threadIdx.x;
    if (i < D_SRC * D_REL) {
        int k = i >> 7;          // 0..255
        int n = i & 127;         // 0..127
        float v = W[i];          // W[k][n]
        __nv_bfloat16 h = __float2bfloat16(v);
        g_wt_hi[n * D_SRC + k] = h;
        g_wt_lo[n * D_SRC + k] = __float2bfloat16(v - __bfloat162float(h));
    }
}

// --------------------- HMMA GEMM -------------------------------------------
// Per CTA: C[128, 128] = A[128, 256] @ W^T, bf16 hi/lo 3-term split.
// SMEM: A_hi[128x64] | A_lo | B_hi[128n x 64k] | B_lo, bf16, SW128.
// Warp grid 4(m) x 2(n): warp (wm, wn) -> rows [32wm,32wm+32), cols [64wn,64wn+64).

#define OFF_AH 0
#define OFF_AL 16384
#define OFF_BH 32768
#define OFF_BL 49152
#define GEMM_SMEM (65536 + 128)

__global__ __launch_bounds__(256) void mma_gemm_kernel(
    const float* __restrict__ A, float* __restrict__ C, int M)
{
    extern __shared__ char smraw[];
    uint32_t rawb = smem_u32(smraw);
    uint32_t smb  = (rawb + 127u) & ~127u;
    char*    sm   = smraw + (smb - rawb);

    const int tid  = threadIdx.x;
    const int wid  = tid >> 5;
    const int lane = tid & 31;
    const int row0 = blockIdx.x * 128;
    const int wm   = wid & 3;         // m group: rows [32wm, 32wm+32)
    const int wn   = wid >> 2;        // n group: cols [64wn, 64wn+64)

    // acc[mt][nt][4]: mt in {0,1} (16-row tiles), nt in 0..7 (8-col tiles)
    float acc[2][8][4];
    #pragma unroll
    for (int mt = 0; mt < 2; mt++)
        #pragma unroll
        for (int nt = 0; nt < 8; nt++)
            #pragma unroll
            for (int q = 0; q < 4; q++)
                acc[mt][nt][q] = 0.f;

    // ldmatrix per-lane addressing bases
    const int tpid  = lane >> 3;
    const int rowin = lane & 7;
    const int a_mb  = 32 * wm + (tpid & 1) * 8 + rowin;    // + 16*mt
    const int a_kb0 = (tpid >> 1) * 16;
    const int b_kb0 = (tpid & 1) * 16;
    const int b_nrb = 64 * wn + (tpid >> 1) * 8 + rowin;   // + 16*p

    for (int kc = 0; kc < 4; kc++) {
        // ---- B chunk [128 n x 64 k] hi/lo via cp.async (overlaps A convert) ----
        #pragma unroll
        for (int i = 0; i < 4; i++) {
            int idx = tid + i * 256;
            int r   = idx >> 3;
            int k0  = (idx & 7) * 8;
            uint32_t off = SW128(r * 128 + k0 * 2);
            const char* gh = (const char*)(g_wt_hi + r * D_SRC + kc * 64 + k0);
            const char* gl = (const char*)(g_wt_lo + r * D_SRC + kc * 64 + k0);
            CP_ASYNC16(smb + OFF_BH + off, gh);
            CP_ASYNC16(smb + OFF_BL + off, gl);
        }
        CP_COMMIT();

        // ---- A chunk [128 x 64] fp32 -> bf16 hi/lo ----
        #pragma unroll
        for (int i = 0; i < 4; i++) {
            int idx = tid + i * 256;
            int r   = idx >> 3;
            int k0  = (idx & 7) * 8;
            int gr  = row0 + r;
            float4 v0 = make_float4(0.f, 0.f, 0.f, 0.f);
            float4 v1 = v0;
            if (gr < M) {
                const float* ap = A + (size_t)gr * D_SRC + kc * 64 + k0;
                v0 = *reinterpret_cast<const float4*>(ap);
                v1 = *reinterpret_cast<const float4*>(ap + 4);
            }
            float fv[8] = {v0.x, v0.y, v0.z, v0.w, v1.x, v1.y, v1.z, v1.w};
            __nv_bfloat16 h[8], l[8];
            #pragma unroll
            for (int j = 0; j < 8; j++) {
                h[j] = __float2bfloat16(fv[j]);
                l[j] = __float2bfloat16(fv[j] - __bfloat162float(h[j]));
            }
            uint32_t off = SW128(r * 128 + k0 * 2);
            *reinterpret_cast<uint4*>(sm + OFF_AH + off) = *reinterpret_cast<uint4*>(h);
            *reinterpret_cast<uint4*>(sm + OFF_AL + off) = *reinterpret_cast<uint4*>(l);
        }
        CP_WAIT0();
        __syncthreads();

        #pragma unroll
        for (int ks = 0; ks < 4; ks++) {
            const int kb = ks * 32;   // byte offset within 128B row
            uint32_t ah[2][4], al[2][4];
            #pragma unroll
            for (int mt = 0; mt < 2; mt++) {
                uint32_t aoff = SW128((a_mb + 16 * mt) * 128 + kb + a_kb0);
                ldm_x4(ah[mt], smb + OFF_AH + aoff);
                ldm_x4(al[mt], smb + OFF_AL + aoff);
            }

            #pragma unroll
            for (int p = 0; p < 4; p++) {
                uint32_t bh[4], bl[4];
                uint32_t boff = SW128((b_nrb + 16 * p) * 128 + kb + b_kb0);
                // K-major [n][k] B: NON-trans ldmatrix -> col-major k16n8 frags
                ldm_x4(bh, smb + OFF_BH + boff);
                ldm_x4(bl, smb + OFF_BL + boff);
                #pragma unroll
                for (int mt = 0; mt < 2; mt++) {
                    mma_bf16(acc[mt][2 * p],     ah[mt], bh[0], bh[1]);
                    mma_bf16(acc[mt][2 * p],     ah[mt], bl[0], bl[1]);
                    mma_bf16(acc[mt][2 * p],     al[mt], bh[0], bh[1]);
                    mma_bf16(acc[mt][2 * p + 1], ah[mt], bh[2], bh[3]);
                    mma_bf16(acc[mt][2 * p + 1], ah[mt], bl[2], bl[3]);
                    mma_bf16(acc[mt][2 * p + 1], al[mt], bh[2], bh[3]);
                }
            }
        }
        __syncthreads();
    }

    // ---- epilogue ----
    int cb = (lane & 3) * 2;
    #pragma unroll
    for (int mt = 0; mt < 2; mt++) {
        int r_lo = row0 + 32 * wm + 16 * mt + (lane >> 2);
        #pragma unroll
        for (int nt = 0; nt < 8; nt++) {
            int col = 64 * wn + nt * 8 + cb;
            if (r_lo < M)
                *reinterpret_cast<float2*>(C + (size_t)r_lo * D_REL + col) =
                    make_float2(acc[mt][nt][0], acc[mt][nt][1]);
            if (r_lo + 8 < M)
                *reinterpret_cast<float2*>(C + (size_t)(r_lo + 8) * D_REL + col) =
                    make_float2(acc[mt][nt][2], acc[mt][nt][3]);
        }
    }
}

// --------------------------- CSR build -------------------------------------

__global__ void zero_cnt_kernel(int n) {
    int i = blockIdx.x * blockDim.x + threadIdx.x;
    if (i < n) g_cnt[i] = 0;
    if (i == 0) g_total = 0;
}

__global__ void count_kernel(const int* __restrict__ row, int E) {
    int e = blockIdx.x * blockDim.x + threadIdx.x;
    if (e < E) atomicAdd(&g_cnt[row[e]], 1);
}

// Bump allocator: contiguous segment per row, rows unordered globally.
__global__ void alloc_kernel(float* __restrict__ deg, int N) {
    __shared__ int s[256];
    __shared__ int blockBase;
    int b = blockIdx.x, tid = threadIdx.x;
    int base = b * 1024 + tid * 4;

    int c[4];
    int sum = 0;
    #pragma unroll
    for (int i = 0; i < 4; i++) {
        int idx = base + i;
        c[i] = (idx < N) ? g_cnt[idx] : 0;
        sum += c[i];
    }
    s[tid] = sum;
    __syncthreads();
    for (int off = 1; off < 256; off <<= 1) {
        int t = (tid >= off) ? s[tid - off] : 0;
        __syncthreads();
        s[tid] += t;
        __syncthreads();
    }
    if (tid == 255) blockBase = atomicAdd(&g_total, s[255]);
    __syncthreads();

    int pos = blockBase + s[tid] - sum;
    #pragma unroll
    for (int i = 0; i < 4; i++) {
        int idx = base + i;
        if (idx < N) {
            g_ptr[idx]    = pos;
            g_cursor[idx] = pos;
            deg[idx]      = fmaxf((float)c[i], 1.0f);
            pos += c[i];
        }
    }
}

__global__ void fill_kernel(const int* __restrict__ row,
                            const int* __restrict__ col, int E) {
    int e = blockIdx.x * blockDim.x + threadIdx.x;
    if (e < E) {
        int r = row[e];
        int pos = atomicAdd(&g_cursor[r], 1);
        g_col[pos] = col[e];
    }
}

// -------------------- aggregate: warp per dst row --------------------------

__global__ __launch_bounds__(256) void aggregate_kernel(
    const float* __restrict__ srcp, float* __restrict__ dst, int N)
{
    int warp = (blockIdx.x * blockDim.x + threadIdx.x) >> 5;
    if (warp >= N) return;
    int lane = threadIdx.x & 31;

    int beg = g_ptr[warp];
    int cnt = g_cnt[warp];
    int end = beg + cnt;

    float4 acc = make_float4(0.f, 0.f, 0.f, 0.f);
    int e = beg;
    for (; e + 1 < end; e += 2) {
        int c0 = g_col[e], c1 = g_col[e + 1];
        float4 v0 = *reinterpret_cast<const float4*>(srcp + (size_t)c0 * D_REL + lane * 4);
        float4 v1 = *reinterpret_cast<const float4*>(srcp + (size_t)c1 * D_REL + lane * 4);
        acc.x += v0.x + v1.x; acc.y += v0.y + v1.y;
        acc.z += v0.z + v1.z; acc.w += v0.w + v1.w;
    }
    if (e < end) {
        int c0 = g_col[e];
        float4 v0 = *reinterpret_cast<const float4*>(srcp + (size_t)c0 * D_REL + lane * 4);
        acc.x += v0.x; acc.y += v0.y; acc.z += v0.z; acc.w += v0.w;
    }

    float invd = 1.0f / fmaxf((float)cnt, 1.0f);
    acc.x *= invd; acc.y *= invd; acc.z *= invd; acc.w *= invd;
    *reinterpret_cast<float4*>(dst + (size_t)warp * D_REL + lane * 4) = acc;
}

// ------------------------------ launch -------------------------------------

extern "C" void kernel_launch(void* const* d_in, const int* in_sizes, int n_in,
                              void* d_out, int out_size)
{
    const float* x_src    = (const float*)d_in[0];
    const float* W_src    = (const float*)d_in[2];
    const int*   edge_row = (const int*)d_in[4];
    const int*   edge_col = (const int*)d_in[5];

    const int M    = in_sizes[0] / D_SRC;   // N_SRC
    const int Ndst = in_sizes[1] / 64;      // N_DST
    const int E    = in_sizes[4];

    float* out  = (float*)d_out;
    float* dst  = out;                                 // [Ndst, 128]
    float* srcp = out + (size_t)Ndst * D_REL;          // [M, 128]
    float* deg  = srcp + (size_t)M * D_REL;            // [Ndst]

    const int NB = (Ndst + 1023) / 1024;

    static int once = 0;
    if (!once) {
        cudaFuncSetAttribute(mma_gemm_kernel,
                             cudaFuncAttributeMaxDynamicSharedMemorySize, GEMM_SMEM);
        once = 1;
    }

    // W split + tensor-core GEMM
    wsplit_kernel<<<(D_SRC * D_REL + 255) / 256, 256>>>(W_src);
    mma_gemm_kernel<<<(M + 127) / 128, 256, GEMM_SMEM>>>(x_src, srcp, M);

    // CSR build: zero -> count -> bump-alloc -> fill
    zero_cnt_kernel<<<(Ndst + 255) / 256, 256>>>(Ndst);
    count_kernel<<<(E + 255) / 256, 256>>>(edge_row, E);
    alloc_kernel<<<NB, 256>>>(deg, Ndst);
    fill_kernel<<<(E + 255) / 256, 256>>>(edge_row, edge_col, E);

    // Gather-aggregate
    aggregate_kernel<<<(Ndst * 32 + 255) / 256, 256>>>(srcp, dst, Ndst);
}